// round 15
// baseline (speedup 1.0000x reference)
#include <cuda_runtime.h>
#include <math.h>

// Problem constants
#define BSZ 32
#define SSZ 1024
#define DSZ 1024

typedef unsigned long long ull;

// Scratch buffers (device globals — no allocation allowed in kernel_launch).
// buf0: Z0 (= x@W0) -> overwritten in place with h0 (time-major [S,B,D])
// buf1: Z1 (= h0@W1) (time-major [S,B,D])
__device__ float g_buf0[(size_t)BSZ * SSZ * DSZ];
__device__ float g_buf1[(size_t)BSZ * SSZ * DSZ];
// Paired h state, double-buffered by parity: g_hp[p][b][j] = (h[b][j], h[b][j+512])
__device__ float2 g_hp[2][BSZ][DSZ / 2];

// Monotonic per-b-group barrier counters (4 groups, each in its own 128B line)
// + global cleanup counter. Zero-init; restored at launch end.
__device__ unsigned g_bar_cnt[4 * 32];
__device__ unsigned g_cleanup;

// ---------------------------------------------------------------------------
// Packed f32x2 helpers (sm_100+). Each lane is an independent IEEE fp32 FMA —
// bit-identical to two scalar fmaf chains.
// ---------------------------------------------------------------------------
__device__ __forceinline__ ull fma2(ull a, ull b, ull c) {
    ull d;
    asm("fma.rn.f32x2 %0, %1, %2, %3;" : "=l"(d) : "l"(a), "l"(b), "l"(c));
    return d;
}
__device__ __forceinline__ void unpack2(ull v, float& lo, float& hi) {
    asm("mov.b64 {%0, %1}, %2;" : "=f"(lo), "=f"(hi) : "l"(v));
}
__device__ __forceinline__ ull pack2(float lo, float hi) {
    ull r;
    asm("mov.b64 %0, {%1, %2};" : "=l"(r) : "f"(lo), "f"(hi));
    return r;
}

// ---------------------------------------------------------------------------
// Reference arithmetic (validated bit-exact in rounds 9-13):
//   dot  = split-K=2: two ascending fp32 fmaf chains of 512, combined s0+s1
//   z    = (x@W + h@U) + b  (rn adds, that order)
//   tanh = XLA fast-tanh with_fma: clamp +-7.99881172180175781, FMA Horner,
//          rn divide, |x|<0.0004 passthrough.
// ---------------------------------------------------------------------------
__device__ __forceinline__ float xla_tanh(float x) {
    const float kMax = 7.99881172180175781f;
    float ax = fabsf(x);
    float xc = fminf(fmaxf(x, -kMax), kMax);
    float x2 = __fmul_rn(xc, xc);
    float p = -2.76076847742355e-16f;
    p = fmaf(x2, p, 2.00018790482477e-13f);
    p = fmaf(x2, p, -8.60467152213735e-11f);
    p = fmaf(x2, p, 5.12229709037114e-08f);
    p = fmaf(x2, p, 1.48572235717979e-05f);
    p = fmaf(x2, p, 6.37261928875436e-04f);
    p = fmaf(x2, p, 4.89352455891786e-03f);
    p = __fmul_rn(xc, p);
    float q = 1.19825839466702e-06f;
    q = fmaf(x2, q, 1.18534705686654e-04f);
    q = fmaf(x2, q, 2.26843463243900e-03f);
    q = fmaf(x2, q, 4.89352518554385e-03f);
    float r = __fdiv_rn(p, q);
    return (ax < 0.0004f) ? x : r;
}

// ---------------------------------------------------------------------------
// FFMA2 GEMM: C = A @ W (no bias). The two split-K chains (k<512, k>=512) are
// independent -> packed into f32x2 lanes; pairs built at SMEM-store time.
// Lane0 accumulates k=0..511 ascending, lane1 k=512..1023; final lo+hi (rn).
//   remap=1: A row m = b*S + s  ->  C row = s*B + b   (x -> time-major Z0)
//   remap=0: C row = m
// ---------------------------------------------------------------------------
__global__ __launch_bounds__(256) void gemm_kernel(
    const float* __restrict__ A_ext, int a_sel,
    const float* __restrict__ W,
    int c_sel, int remap)
{
    const int N_ = DSZ, K_ = DSZ;
    const float* A = (a_sel == 0) ? (const float*)g_buf0 : A_ext;
    float* C = (c_sel == 0) ? g_buf0 : g_buf1;

    __shared__ ull As2[8][132];   // [klo][m] pairs, padded row
    __shared__ ull Bs2[8][66];    // [klo][n] pairs, padded row

    const int tid = threadIdx.x;
    const int tx = tid & 15;
    const int ty = tid >> 4;
    const int m0 = blockIdx.y * 128;
    const int n0 = blockIdx.x * 64;

    ull acc2[8][4];
#pragma unroll
    for (int i = 0; i < 8; i++)
#pragma unroll
        for (int j = 0; j < 4; j++) acc2[i][j] = 0ull;

    const int arow = tid >> 1;
    const int akq = (tid & 1) * 4;
    const int brow = tid >> 4;
    const int bnq = (tid & 15) * 4;

    for (int kt = 0; kt < 512; kt += 8) {
        {
            float4 lo = *(const float4*)&A[(size_t)(m0 + arow) * K_ + kt + akq];
            float4 hi = *(const float4*)&A[(size_t)(m0 + arow) * K_ + kt + 512 + akq];
            As2[akq + 0][arow] = pack2(lo.x, hi.x);
            As2[akq + 1][arow] = pack2(lo.y, hi.y);
            As2[akq + 2][arow] = pack2(lo.z, hi.z);
            As2[akq + 3][arow] = pack2(lo.w, hi.w);
        }
        if (tid < 128) {
            float4 blo = *(const float4*)&W[(size_t)(kt + brow) * N_ + n0 + bnq];
            float4 bhi = *(const float4*)&W[(size_t)(kt + 512 + brow) * N_ + n0 + bnq];
            Bs2[brow][bnq + 0] = pack2(blo.x, bhi.x);
            Bs2[brow][bnq + 1] = pack2(blo.y, bhi.y);
            Bs2[brow][bnq + 2] = pack2(blo.z, bhi.z);
            Bs2[brow][bnq + 3] = pack2(blo.w, bhi.w);
        }
        __syncthreads();

#pragma unroll
        for (int kk = 0; kk < 8; kk++) {
            ull a2[8], b2[4];
#pragma unroll
            for (int i = 0; i < 8; i++) a2[i] = As2[kk][ty * 8 + i];
#pragma unroll
            for (int j = 0; j < 4; j++) b2[j] = Bs2[kk][tx * 4 + j];
#pragma unroll
            for (int i = 0; i < 8; i++)
#pragma unroll
                for (int j = 0; j < 4; j++)
                    acc2[i][j] = fma2(a2[i], b2[j], acc2[i][j]);
        }
        __syncthreads();
    }

#pragma unroll
    for (int i = 0; i < 8; i++) {
        int m = m0 + ty * 8 + i;
        int orow = remap ? ((m & (SSZ - 1)) * BSZ + (m >> 10)) : m;
        float lo, hi;
        float4 v;
        unpack2(acc2[i][0], lo, hi); v.x = __fadd_rn(lo, hi);
        unpack2(acc2[i][1], lo, hi); v.y = __fadd_rn(lo, hi);
        unpack2(acc2[i][2], lo, hi); v.z = __fadd_rn(lo, hi);
        unpack2(acc2[i][3], lo, hi); v.w = __fadd_rn(lo, hi);
        *(float4*)&C[(size_t)orow * N_ + n0 + tx * 4] = v;
    }
}

// ---------------------------------------------------------------------------
// Persistent recurrent kernel, 64 threads/CTA, 2x2 register tiling.
// Grid = 128 CTAs = 4 b-groups x 32 c-groups; CTA covers b in [b0,b0+8),
// c in [c0,c0+32). Thread (bq = tid>>4, cq = tid&15) owns outputs
// (2bq, 2bq+1) x (2cq, 2cq+1): each loaded h-vector feeds 2 columns and
// each U-vector feeds 2 rows -> SMEM crossbar lane-bytes halved vs 1x1
// (the measured binding term). Each of the 4 accumulators is its own
// ascending split-K=2 fma2 chain — bit-exact.
// Barrier: monotonic per-group counter, target 32*(t+1); no flag/reset.
// Dynamic SMEM: Usp 32x514 float2 (131.6KB) + Hs 8x514 float2 (32.9KB).
// ---------------------------------------------------------------------------
#define USP_STRIDE 514
#define HS_STRIDE 514

__global__ __launch_bounds__(64, 1) void rnn_kernel(
    int z_sel, const float* __restrict__ U, const float* __restrict__ bias,
    float* H_ext, int h_is_ext, long hStrideT, long hStrideB)
{
    extern __shared__ __align__(16) float2 smem[];
    float2* Usp = smem;                      // [32][USP_STRIDE]
    float2* Hs = smem + 32 * USP_STRIDE;     // [8][HS_STRIDE]

    const float* Z = z_sel ? (const float*)g_buf1 : (const float*)g_buf0;
    float* H = h_is_ext ? H_ext : g_buf0;

    const int tid = threadIdx.x;
    const int bid = blockIdx.x;
    const int grp = bid >> 5;                // b-group 0..3
    const int b0 = grp * 8;                  // 8 b-rows per group
    const int c0 = (bid & 31) * 32;          // 32 c-groups of 32

    unsigned* bar_cnt = &g_bar_cnt[grp * 32];

    // Stage paired U slice: Usp[c][j] = (U[j*D + c0+c], U[(j+512)*D + c0+c])
    for (int i = tid; i < 32 * 512; i += 64) {
        int c = i & 31;
        int j = i >> 5;
        float2 pr;
        pr.x = U[(size_t)j * DSZ + c0 + c];
        pr.y = U[(size_t)(j + 512) * DSZ + c0 + c];
        Usp[c * USP_STRIDE + j] = pr;
    }
    __syncthreads();

    // 2x2 tile ownership
    const int bq = tid >> 4;                 // 0..3
    const int cq = tid & 15;                 // 0..15
    const int bl0 = 2 * bq, bl1 = bl0 + 1;   // local b rows
    const int cl0 = 2 * cq, cl1 = cl0 + 1;   // local c cols
    const int bA = b0 + bl0, bB = b0 + bl1;  // global b
    const int cgA = c0 + cl0, cgB = c0 + cl1;// global c

    const float bvA = bias[cgA];
    const float bvB = bias[cgB];
    const int chi = (cgA >= 512) ? 1 : 0;    // uniform per CTA (32-aligned)
    const int jjA = cgA & 511, jjB = cgB & 511;

    const ulonglong2* hrow0 = (const ulonglong2*)&Hs[bl0 * HS_STRIDE];
    const ulonglong2* hrow1 = (const ulonglong2*)&Hs[bl1 * HS_STRIDE];
    const ulonglong2* urow0 = (const ulonglong2*)&Usp[cl0 * USP_STRIDE];
    const ulonglong2* urow1 = (const ulonglong2*)&Usp[cl1 * USP_STRIDE];

    for (int t = 0; t < SSZ; ++t) {
        if (t > 0) {
            // Bulk load group's 8 paired h rows (32KB contiguous) into SMEM.
            const ulonglong2* src =
                (const ulonglong2*)&g_hp[(t - 1) & 1][b0][0];
#pragma unroll
            for (int s = 0; s < 32; s++) {
                int g = tid + s * 64;             // 0..2047
                int r = g >> 8;
                int q2 = g & 255;
                ulonglong2 v = __ldcg(src + g);
                *(ulonglong2*)&Hs[r * HS_STRIDE + q2 * 2] = v;
            }
            __syncthreads();
        }

        // Z loads issued early (consumed after the dot) — latency hidden.
        const float* zrowA = &Z[((size_t)t * BSZ + bA) * DSZ];
        const float* zrowB = &Z[((size_t)t * BSZ + bB) * DSZ];
        float zW00 = __ldcg(zrowA + cgA);
        float zW01 = __ldcg(zrowA + cgB);
        float zW10 = __ldcg(zrowB + cgA);
        float zW11 = __ldcg(zrowB + cgB);

        float st00 = 0.f, st01 = 0.f, st10 = 0.f, st11 = 0.f;
        if (t > 0) {
            // 2-deep prefetch; 4 independent ascending fma2 chains (bit-exact).
            ull s00 = 0, s01 = 0, s10 = 0, s11 = 0;
            ulonglong2 h0b[2], h1b[2], u0b[2], u1b[2];
            h0b[0] = hrow0[0]; h1b[0] = hrow1[0];
            u0b[0] = urow0[0]; u1b[0] = urow1[0];
            h0b[1] = hrow0[1]; h1b[1] = hrow1[1];
            u0b[1] = urow0[1]; u1b[1] = urow1[1];
#pragma unroll 8
            for (int q = 0; q < 256; q++) {
                const int sl = q & 1;
                ulonglong2 hv0 = h0b[sl], hv1 = h1b[sl];
                ulonglong2 uv0 = u0b[sl], uv1 = u1b[sl];
                if (q < 254) {
                    h0b[sl] = hrow0[q + 2];
                    h1b[sl] = hrow1[q + 2];
                    u0b[sl] = urow0[q + 2];
                    u1b[sl] = urow1[q + 2];
                }
                s00 = fma2(hv0.x, uv0.x, s00);
                s00 = fma2(hv0.y, uv0.y, s00);
                s01 = fma2(hv0.x, uv1.x, s01);
                s01 = fma2(hv0.y, uv1.y, s01);
                s10 = fma2(hv1.x, uv0.x, s10);
                s10 = fma2(hv1.y, uv0.y, s10);
                s11 = fma2(hv1.x, uv1.x, s11);
                s11 = fma2(hv1.y, uv1.y, s11);
            }
            float a, bta;
            unpack2(s00, a, bta); st00 = __fadd_rn(a, bta);
            unpack2(s01, a, bta); st01 = __fadd_rn(a, bta);
            unpack2(s10, a, bta); st10 = __fadd_rn(a, bta);
            unpack2(s11, a, bta); st11 = __fadd_rn(a, bta);
        }

        float h00 = xla_tanh(__fadd_rn(__fadd_rn(zW00, st00), bvA));
        float h01 = xla_tanh(__fadd_rn(__fadd_rn(zW01, st01), bvB));
        float h10 = xla_tanh(__fadd_rn(__fadd_rn(zW10, st10), bvA));
        float h11 = xla_tanh(__fadd_rn(__fadd_rn(zW11, st11), bvB));

        // normal layout (consumed by next GEMM / final output)
        float* HA = H + (size_t)t * hStrideT + (size_t)bA * hStrideB;
        float* HB = H + (size_t)t * hStrideT + (size_t)bB * hStrideB;
        HA[cgA] = h00; HA[cgB] = h01;
        HB[cgA] = h10; HB[cgB] = h11;
        // paired layout for next step's bulk load
        float2* hpA = &g_hp[t & 1][bA][0];
        float2* hpB = &g_hp[t & 1][bB][0];
        ((float*)&hpA[jjA])[chi] = h00;
        ((float*)&hpA[jjB])[chi] = h01;
        ((float*)&hpB[jjA])[chi] = h10;
        ((float*)&hpB[jjB])[chi] = h11;

        if (t != SSZ - 1) {
            // Monotonic per-group barrier: arrive +1, poll for 32*(t+1).
            __syncthreads();
            if (tid == 0) {
                __threadfence();
                atomicAdd(bar_cnt, 1u);
                unsigned want = 32u * (unsigned)(t + 1);
                unsigned v;
                do {
                    asm volatile("ld.acquire.gpu.u32 %0, [%1];"
                                 : "=r"(v) : "l"(bar_cnt) : "memory");
                } while (v < want);
            }
            __syncthreads();
        }
    }

    // Cleanup: last-arriving CTA (grid-wide) restores all barrier state so
    // the next launch / graph replay starts from zero. Everyone else exits;
    // no thread reads the counters after its final poll.
    __syncthreads();
    if (tid == 0) {
        __threadfence();
        unsigned prev = atomicAdd(&g_cleanup, 1u);
        if (prev == 127u) {
            for (int g = 0; g < 4; g++) g_bar_cnt[g * 32] = 0u;
            g_cleanup = 0u;
            __threadfence();
        }
    }
}

// ---------------------------------------------------------------------------
// Launch: Z0 = x@W0  ->  scan layer0  ->  Z1 = h0@W1  ->  scan layer1
// ---------------------------------------------------------------------------
extern "C" void kernel_launch(void* const* d_in, const int* in_sizes, int n_in,
                              void* d_out, int out_size)
{
    const float* x  = (const float*)d_in[0];   // [B,S,D]
    const float* Wh = (const float*)d_in[1];   // [L,D,D]
    const float* Uh = (const float*)d_in[2];   // [L,D,D]
    const float* bb = (const float*)d_in[3];   // [L,D]
    float* out = (float*)d_out;                // [B,S,D]

    const int DD = DSZ * DSZ;
    dim3 ggrid(DSZ / 64, (BSZ * SSZ) / 128);   // (16, 256)

    const int smem_bytes = (32 * USP_STRIDE + 8 * HS_STRIDE) * sizeof(float2);
    cudaFuncSetAttribute(rnn_kernel,
                         cudaFuncAttributeMaxDynamicSharedMemorySize,
                         smem_bytes);

    // Layer 0: Z0 = x @ W0 (remap rows to time-major), into buf0
    gemm_kernel<<<ggrid, 256>>>(x, /*a_sel=*/-1, Wh, /*c_sel=*/0, /*remap=*/1);

    // Layer 0 scan: h0_t = tanh((Z0_t + h0_{t-1}@U0) + b0), in place in buf0
    rnn_kernel<<<128, 64, smem_bytes>>>(/*z_sel=*/0, Uh, bb, nullptr,
                                        /*h_is_ext=*/0,
                                        (long)(BSZ * DSZ), (long)DSZ);

    // Layer 1: Z1 = h0 @ W1 (rows already time-major), into buf1
    gemm_kernel<<<ggrid, 256>>>(nullptr, /*a_sel=*/0, Wh + DD,
                                /*c_sel=*/1, /*remap=*/0);

    // Layer 1 scan: out_t = tanh((Z1_t + out_{t-1}@U1) + b1), to d_out [B,S,D]
    rnn_kernel<<<128, 64, smem_bytes>>>(/*z_sel=*/1, Uh + DD, bb + DSZ, out,
                                        /*h_is_ext=*/1,
                                        (long)DSZ, (long)((size_t)SSZ * DSZ));
}